// round 4
// baseline (speedup 1.0000x reference)
#include <cuda_runtime.h>
#include <cstdint>

#define HW   48000
#define NPTS 12000
#define KNN  16

using ull = unsigned long long;

__device__ __forceinline__ ull pack2(float x, float y) {
    ull r; asm("mov.b64 %0, {%1, %2};" : "=l"(r) : "f"(x), "f"(y)); return r;
}
__device__ __forceinline__ float2 unpack2(ull v) {
    float2 r; asm("mov.b64 {%0, %1}, %2;" : "=f"(r.x), "=f"(r.y) : "l"(v)); return r;
}
__device__ __forceinline__ ull fma2(ull a, ull b, ull c) {
    ull d; asm("fma.rn.f32x2 %0, %1, %2, %3;" : "=l"(d) : "l"(a), "l"(b), "l"(c)); return d;
}

// transposed feature map: [b*HW + p][64], contiguous 256B per pixel
__device__ __align__(16) float g_ft[2u * HW * 64u];

// ---------------------------------------------------------------------------
// Kernel 1: f = leaky_relu(mlp_w @ features + mlp_b), transposed to [pix][c]
// 375 blocks x 256 threads. Thread: 4 pixels x 16 channels (register tile).
// smem (dynamic): ws[64][68] + ftile[8][264] + stage[256][68]
// ---------------------------------------------------------------------------
#define WS_PAD 68
#define FT_PAD 264
#define ST_PAD 68

__global__ void __launch_bounds__(256) k_feat_mlp(
    const float* __restrict__ feat,   // [B,64,HW]
    const float* __restrict__ mw,     // [64,64] [cout][cin]
    const float* __restrict__ mb)     // [64]
{
    extern __shared__ float sm[];
    float* ws    = sm;                       // [64][WS_PAD]  transposed: ws[ci][c]
    float* ftile = ws + 64 * WS_PAD;         // [8][FT_PAD]
    float* stage = ftile + 8 * FT_PAD;       // [256][ST_PAD]
    __shared__ float bsh[64];

    const int tid = threadIdx.x;
    for (int i = tid; i < 4096; i += 256) {
        int c = i >> 6, ci = i & 63;
        ws[ci * WS_PAD + c] = mw[i];
    }
    if (tid < 64) bsh[tid] = mb[tid];
    __syncthreads();

    const int cg  = tid & 3;          // channel group: channels 16*cg..16*cg+15
    const int pxq = tid >> 2;         // pixel quad: local px 4*pxq..4*pxq+3
    const long gpix0 = (long)blockIdx.x * 256;

    ull acc[4][8];
#pragma unroll
    for (int i = 0; i < 4; i++)
#pragma unroll
        for (int q = 0; q < 8; q++)
            acc[i][q] = pack2(bsh[16 * cg + 2 * q], bsh[16 * cg + 2 * q + 1]);

    for (int chunk = 0; chunk < 8; chunk++) {
        // load feat tile: 8 input channels x 256 pixels, coalesced
        for (int i = tid; i < 2048; i += 256) {
            int ci = i >> 8, px = i & 255;
            long pix = gpix0 + px;
            int bb = (pix >= HW) ? 1 : 0;
            int pp = (int)(pix - (long)bb * HW);
            ftile[ci * FT_PAD + px] =
                feat[(size_t)bb * 64 * HW + (size_t)(chunk * 8 + ci) * HW + pp];
        }
        __syncthreads();

#pragma unroll
        for (int cc = 0; cc < 8; cc++) {
            const float4 v = *reinterpret_cast<const float4*>(
                &ftile[cc * FT_PAD + 4 * pxq]);
            const ull* wrow = reinterpret_cast<const ull*>(
                &ws[(chunk * 8 + cc) * WS_PAD + 16 * cg]);
            ull wp[8];
#pragma unroll
            for (int q = 0; q < 8; q++) wp[q] = wrow[q];
            const ull vv0 = pack2(v.x, v.x), vv1 = pack2(v.y, v.y);
            const ull vv2 = pack2(v.z, v.z), vv3 = pack2(v.w, v.w);
#pragma unroll
            for (int q = 0; q < 8; q++) {
                acc[0][q] = fma2(wp[q], vv0, acc[0][q]);
                acc[1][q] = fma2(wp[q], vv1, acc[1][q]);
                acc[2][q] = fma2(wp[q], vv2, acc[2][q]);
                acc[3][q] = fma2(wp[q], vv3, acc[3][q]);
            }
        }
        __syncthreads();
    }

    // leaky relu, stage as [px][ch]
#pragma unroll
    for (int i = 0; i < 4; i++) {
        const int px = 4 * pxq + i;
        float2* srow = reinterpret_cast<float2*>(&stage[px * ST_PAD + 16 * cg]);
#pragma unroll
        for (int q = 0; q < 8; q++) {
            float2 t = unpack2(acc[i][q]);
            t.x = (t.x >= 0.f) ? t.x : 0.1f * t.x;
            t.y = (t.y >= 0.f) ? t.y : 0.1f * t.y;
            srow[q] = t;
        }
    }
    __syncthreads();

    // coalesced store: 2 pixel rows (512B contiguous) per warp instruction
    const int warp = tid >> 5, lane = tid & 31;
    const int r2 = lane >> 4, q4 = lane & 15;
    const size_t gbase = (size_t)gpix0 * 64;
    for (int r = warp * 32; r < warp * 32 + 32; r += 2) {
        const int px = r + r2;
        float4 val = *reinterpret_cast<const float4*>(&stage[px * ST_PAD + 4 * q4]);
        *reinterpret_cast<float4*>(&g_ft[gbase + (size_t)px * 64 + 4 * q4]) = val;
    }
}

// ---------------------------------------------------------------------------
// Kernel 2: gather + weight-net + f*wgt max over k
// 750 blocks x 256 threads = 4 warp-PAIRS; pair handles 8 points sequentially,
// each warp of the pair owns 32 output channels. Prefetch next point's gathers.
// ---------------------------------------------------------------------------
__global__ void __launch_bounds__(256) k_gather(
    const float* __restrict__ xyz,    // [B,3,HW]
    const float* __restrict__ sxyz,   // [B,3,N]
    const int*   __restrict__ knn,    // [B,N,16]
    const int*   __restrict__ mask,   // [B,N,16] (bool widened to int32)
    const float* __restrict__ w1, const float* __restrict__ b1,
    const float* __restrict__ w2, const float* __restrict__ b2,
    const float* __restrict__ w3, const float* __restrict__ b3,
    float* __restrict__ out)          // [B,64,N]
{
    __shared__ float s_w1[24];
    __shared__ float s_b1[8];
    __shared__ float s_w2[256];
    __shared__ float s_b2[32];
    __shared__ __align__(16) float s_h2[4][16][36];  // pad 36: 16B-aligned rows
    __shared__ int   s_idx[4][16];
    __shared__ float s_mf[4][16];
    __shared__ float s_out[64][33];

    const int tid = threadIdx.x;
    const int warp = tid >> 5, lane = tid & 31;
    const int pp = warp >> 1;           // pair 0..3
    const int parity = warp & 1;        // which 32 channels

    if (tid < 24) s_w1[tid] = w1[tid];
    if (tid < 8)  s_b1[tid] = b1[tid];
    if (tid < 32) s_b2[tid] = b2[tid];
    s_w2[tid] = w2[tid];                // 256 threads, 256 elements

    // this lane's single channel; w3 row packed over reduction dim
    const int c = parity * 32 + lane;
    ull w3p[16];
    const ull* w3u = reinterpret_cast<const ull*>(w3);
#pragma unroll
    for (int e = 0; e < 16; e++) w3p[e] = w3u[c * 16 + e];
    const float b3c = b3[c];
    __syncthreads();

    const int b = blockIdx.x / 375;
    const int n_block = (blockIdx.x % 375) * 32;

    const float* xyz_b = xyz + (size_t)b * 3 * HW;
    const float* sx_b  = sxyz + (size_t)b * 3 * NPTS;
    const float* ftb   = g_ft + (size_t)b * HW * 64;

    const int j = lane & 15, sub = lane >> 4;
    const int m0 = parity * 16 + sub * 8;

    // prefetch point 0
    long kb = ((long)b * NPTS + n_block + pp * 8) * KNN + j;
    int   p_nx  = knn[kb];
    int   mv_nx = (mask[kb] != 0);
    float kx_nx = mv_nx ? xyz_b[p_nx] : 0.f;
    float ky_nx = mv_nx ? xyz_b[HW + p_nx] : 0.f;
    float kz_nx = mv_nx ? xyz_b[2 * HW + p_nx] : 0.f;

    for (int pt = 0; pt < 8; pt++) {
        const int slot = pp * 8 + pt;
        const int n = n_block + slot;

        const int p = p_nx;
        const int mv = mv_nx;
        const float kx = kx_nx, ky = ky_nx, kz = kz_nx;

        // issue next point's first-hop loads immediately
        if (pt < 7) {
            const long kb2 = ((long)b * NPTS + n + 1) * KNN + j;
            p_nx  = knn[kb2];
            mv_nx = (mask[kb2] != 0);
        }

        // ---- phase 1: h1, h2 (this lane: neighbor j, h2 slots m0..m0+7)
        const float ox = kx - sx_b[n];
        const float oy = ky - sx_b[NPTS + n];
        const float oz = kz - sx_b[2 * NPTS + n];

        float h1[8];
#pragma unroll
        for (int r = 0; r < 8; r++) {
            float t = s_b1[r] + s_w1[3 * r] * ox + s_w1[3 * r + 1] * oy
                    + s_w1[3 * r + 2] * oz;
            h1[r] = fmaxf(t, 0.f);
        }
#pragma unroll
        for (int mm = 0; mm < 8; mm++) {
            const int m = m0 + mm;
            float t = s_b2[m];
#pragma unroll
            for (int r = 0; r < 8; r++) t += s_w2[m * 8 + r] * h1[r];
            s_h2[pp][j][m] = fmaxf(t, 0.f);
        }
        if (parity == 0 && sub == 0) {
            s_idx[pp][j] = p;
            s_mf[pp][j]  = mv ? 1.f : 0.f;
        }

        // second-hop prefetch for next point (covered by phase 2)
        if (pt < 7) {
            kx_nx = mv_nx ? xyz_b[p_nx] : 0.f;
            ky_nx = mv_nx ? xyz_b[HW + p_nx] : 0.f;
            kz_nx = mv_nx ? xyz_b[2 * HW + p_nx] : 0.f;
        }

        asm volatile("bar.sync %0, %1;" :: "r"(1 + pp), "r"(64) : "memory");

        // ---- phase 2: w3 layer + f*wgt, max over k (2 neighbors interleaved)
        float acc = -3.4e38f;
#pragma unroll
        for (int jj = 0; jj < KNN; jj += 2) {
            const int pA = s_idx[pp][jj],     pB = s_idx[pp][jj + 1];
            const float mfA = s_mf[pp][jj],   mfB = s_mf[pp][jj + 1];
            const float fvA = ftb[(size_t)pA * 64 + c];
            const float fvB = ftb[(size_t)pB * 64 + c];
            const ulonglong2* hA = reinterpret_cast<const ulonglong2*>(&s_h2[pp][jj][0]);
            const ulonglong2* hB = reinterpret_cast<const ulonglong2*>(&s_h2[pp][jj + 1][0]);
            ull a0 = 0ull, a1 = 0ull, bb0 = 0ull, bb1 = 0ull;
#pragma unroll
            for (int e = 0; e < 8; e++) {
                const ulonglong2 ha = hA[e];
                const ulonglong2 hb = hB[e];
                a0  = fma2(w3p[2 * e],     ha.x, a0);
                a1  = fma2(w3p[2 * e + 1], ha.y, a1);
                bb0 = fma2(w3p[2 * e],     hb.x, bb0);
                bb1 = fma2(w3p[2 * e + 1], hb.y, bb1);
            }
            const float2 ra0 = unpack2(a0),  ra1 = unpack2(a1);
            const float2 rb0 = unpack2(bb0), rb1 = unpack2(bb1);
            const float wgA = fmaxf(ra0.x + ra0.y + ra1.x + ra1.y + b3c, 0.f);
            const float wgB = fmaxf(rb0.x + rb0.y + rb1.x + rb1.y + b3c, 0.f);
            acc = fmaxf(acc, fvA * mfA * wgA);
            acc = fmaxf(acc, fvB * mfB * wgB);
        }
        s_out[c][slot] = acc;

        asm volatile("bar.sync %0, %1;" :: "r"(1 + pp), "r"(64) : "memory");
    }
    __syncthreads();

    // coalesced output: [B,64,N]
    float* outb = out + (size_t)b * 64 * NPTS;
    for (int i = tid; i < 2048; i += 256) {
        const int cc = i >> 5, s = i & 31;
        outb[(size_t)cc * NPTS + n_block + s] = s_out[cc][s];
    }
}

extern "C" void kernel_launch(void* const* d_in, const int* in_sizes, int n_in,
                              void* d_out, int out_size)
{
    const float* xyz  = (const float*)d_in[0];
    const float* feat = (const float*)d_in[1];
    const float* sx   = (const float*)d_in[2];
    const int*   knn  = (const int*)d_in[3];
    const int*   mask = (const int*)d_in[4];
    const float* mw = (const float*)d_in[5];
    const float* mb = (const float*)d_in[6];
    const float* w1 = (const float*)d_in[7];
    const float* b1 = (const float*)d_in[8];
    const float* w2 = (const float*)d_in[9];
    const float* b2 = (const float*)d_in[10];
    const float* w3 = (const float*)d_in[11];
    const float* b3 = (const float*)d_in[12];
    float* out = (float*)d_out;

    const int k1_smem = (64 * WS_PAD + 8 * FT_PAD + 256 * ST_PAD) * sizeof(float);
    cudaFuncSetAttribute(k_feat_mlp, cudaFuncAttributeMaxDynamicSharedMemorySize,
                         k1_smem);
    k_feat_mlp<<<375, 256, k1_smem>>>(feat, mw, mb);
    k_gather<<<750, 256>>>(xyz, sx, knn, mask, w1, b1, w2, b2, w3, b3, out);
}

// round 5
// speedup vs baseline: 1.0776x; 1.0776x over previous
#include <cuda_runtime.h>
#include <cstdint>

#define HW   48000
#define NPTS 12000
#define KNN  16

using ull = unsigned long long;

__device__ __forceinline__ ull pack2(float x, float y) {
    ull r; asm("mov.b64 %0, {%1, %2};" : "=l"(r) : "f"(x), "f"(y)); return r;
}
__device__ __forceinline__ float2 unpack2(ull v) {
    float2 r; asm("mov.b64 {%0, %1}, %2;" : "=f"(r.x), "=f"(r.y) : "l"(v)); return r;
}
__device__ __forceinline__ ull fma2(ull a, ull b, ull c) {
    ull d; asm("fma.rn.f32x2 %0, %1, %2, %3;" : "=l"(d) : "l"(a), "l"(b), "l"(c)); return d;
}

// transposed feature map: [b*HW + p][64], contiguous 256B per pixel
__device__ __align__(16) float g_ft[2u * HW * 64u];

// ---------------------------------------------------------------------------
// Kernel 1: f = leaky_relu(mlp_w @ features + mlp_b), transposed to [pix][c]
// 375 blocks x 256 threads. Thread: 4 pixels x 16 channels; ftile chunk
// double-buffered through registers.
// ---------------------------------------------------------------------------
#define WS_PAD 68
#define FT_PAD 264
#define ST_PAD 68

__global__ void __launch_bounds__(256) k_feat_mlp(
    const float* __restrict__ feat,   // [B,64,HW]
    const float* __restrict__ mw,     // [64,64] [cout][cin]
    const float* __restrict__ mb)     // [64]
{
    extern __shared__ float sm[];
    float* ws    = sm;                       // [64][WS_PAD]
    float* ftile = ws + 64 * WS_PAD;         // [8][FT_PAD]
    float* stage = ftile + 8 * FT_PAD;       // [256][ST_PAD]
    __shared__ float bsh[64];

    const int tid = threadIdx.x;
    for (int i = tid; i < 4096; i += 256) {
        int c = i >> 6, ci = i & 63;
        ws[ci * WS_PAD + c] = mw[i];
    }
    if (tid < 64) bsh[tid] = mb[tid];

    const long gpix0 = (long)blockIdx.x * 256;
    // this thread's load pixel (fixed across chunks): px = tid
    const long lpix = gpix0 + tid;
    const int lb = (lpix >= HW) ? 1 : 0;
    const float* fbase = feat + (size_t)lb * 64 * HW + (lpix - (long)lb * HW);

    float pre[8];
#pragma unroll
    for (int t = 0; t < 8; t++) pre[t] = fbase[(size_t)t * HW];
    __syncthreads();

    const int cg  = tid & 3;
    const int pxq = tid >> 2;

    ull acc[4][8];
#pragma unroll
    for (int i = 0; i < 4; i++)
#pragma unroll
        for (int q = 0; q < 8; q++)
            acc[i][q] = pack2(bsh[16 * cg + 2 * q], bsh[16 * cg + 2 * q + 1]);

    for (int chunk = 0; chunk < 8; chunk++) {
#pragma unroll
        for (int t = 0; t < 8; t++) ftile[t * FT_PAD + tid] = pre[t];
        __syncthreads();

        if (chunk < 7) {
#pragma unroll
            for (int t = 0; t < 8; t++)
                pre[t] = fbase[(size_t)((chunk + 1) * 8 + t) * HW];
        }

#pragma unroll
        for (int cc = 0; cc < 8; cc++) {
            const float4 v = *reinterpret_cast<const float4*>(
                &ftile[cc * FT_PAD + 4 * pxq]);
            const ull* wrow = reinterpret_cast<const ull*>(
                &ws[(chunk * 8 + cc) * WS_PAD + 16 * cg]);
            ull wp[8];
#pragma unroll
            for (int q = 0; q < 8; q++) wp[q] = wrow[q];
            const ull vv0 = pack2(v.x, v.x), vv1 = pack2(v.y, v.y);
            const ull vv2 = pack2(v.z, v.z), vv3 = pack2(v.w, v.w);
#pragma unroll
            for (int q = 0; q < 8; q++) {
                acc[0][q] = fma2(wp[q], vv0, acc[0][q]);
                acc[1][q] = fma2(wp[q], vv1, acc[1][q]);
                acc[2][q] = fma2(wp[q], vv2, acc[2][q]);
                acc[3][q] = fma2(wp[q], vv3, acc[3][q]);
            }
        }
        __syncthreads();
    }

    // leaky relu, stage as [px][ch]
#pragma unroll
    for (int i = 0; i < 4; i++) {
        const int px = 4 * pxq + i;
        float2* srow = reinterpret_cast<float2*>(&stage[px * ST_PAD + 16 * cg]);
#pragma unroll
        for (int q = 0; q < 8; q++) {
            float2 t = unpack2(acc[i][q]);
            t.x = (t.x >= 0.f) ? t.x : 0.1f * t.x;
            t.y = (t.y >= 0.f) ? t.y : 0.1f * t.y;
            srow[q] = t;
        }
    }
    __syncthreads();

    const int warp = tid >> 5, lane = tid & 31;
    const int r2 = lane >> 4, q4 = lane & 15;
    const size_t gbase = (size_t)gpix0 * 64;
    for (int r = warp * 32; r < warp * 32 + 32; r += 2) {
        const int px = r + r2;
        float4 val = *reinterpret_cast<const float4*>(&stage[px * ST_PAD + 4 * q4]);
        *reinterpret_cast<float4*>(&g_ft[gbase + (size_t)px * 64 + 4 * q4]) = val;
    }
}

// ---------------------------------------------------------------------------
// Kernel 2: gather + weight-net + f*wgt max over k. Software-pipelined:
// per barrier interval: fv LDGs(pt) | phase1(pt+1) | phase2(pt). One bar/point.
// 750 blocks x 256 threads = 4 warp-pairs; pair handles 8 points.
// ---------------------------------------------------------------------------
__global__ void __launch_bounds__(256, 2) k_gather(
    const float* __restrict__ xyz,    // [B,3,HW]
    const float* __restrict__ sxyz,   // [B,3,N]
    const int*   __restrict__ knn,    // [B,N,16]
    const int*   __restrict__ mask,   // [B,N,16] (bool widened to int32)
    const float* __restrict__ w1, const float* __restrict__ b1,
    const float* __restrict__ w2, const float* __restrict__ b2,
    const float* __restrict__ w3, const float* __restrict__ b3,
    float* __restrict__ out)          // [B,64,N]
{
    __shared__ float s_w1[24];
    __shared__ float s_b1[8];
    __shared__ float s_w2[256];
    __shared__ float s_b2[32];
    __shared__ __align__(16) float s_h2[2][4][16][36];
    __shared__ int   s_idx[2][4][16];
    __shared__ float s_mf[2][4][16];
    __shared__ float s_out[64][33];

    const int tid = threadIdx.x;
    const int warp = tid >> 5, lane = tid & 31;
    const int pp = warp >> 1;
    const int parity = warp & 1;

    if (tid < 24) s_w1[tid] = w1[tid];
    if (tid < 8)  s_b1[tid] = b1[tid];
    if (tid < 32) s_b2[tid] = b2[tid];
    s_w2[tid] = w2[tid];

    const int c = parity * 32 + lane;
    ull w3p[16];
    const ull* w3u = reinterpret_cast<const ull*>(w3);
#pragma unroll
    for (int e = 0; e < 16; e++) w3p[e] = w3u[c * 16 + e];
    const float b3c = b3[c];
    __syncthreads();

    const int b = blockIdx.x / 375;
    const int n_block = (blockIdx.x % 375) * 32;

    const float* xyz_b = xyz + (size_t)b * 3 * HW;
    const float* sx_b  = sxyz + (size_t)b * 3 * NPTS;
    const float* ftb   = g_ft + (size_t)b * HW * 64;

    const int j = lane & 15, sub = lane >> 4;
    const int m0 = parity * 16 + sub * 8;
    const int n0 = n_block + pp * 8;
    const long kb0 = ((long)b * NPTS + n0) * KNN + j;

    // --- prologue: point 0 loads + phase1(0); point 1 loads into pipeline regs
    int   pN; int mN; float xN, yN, zN;
    {
        const int p0 = knn[kb0];
        const int m0v = (mask[kb0] != 0);
        const float kx = m0v ? xyz_b[p0] : 0.f;
        const float ky = m0v ? xyz_b[HW + p0] : 0.f;
        const float kz = m0v ? xyz_b[2 * HW + p0] : 0.f;

        pN = knn[kb0 + KNN];
        mN = (mask[kb0 + KNN] != 0);
        xN = mN ? xyz_b[pN] : 0.f;
        yN = mN ? xyz_b[HW + pN] : 0.f;
        zN = mN ? xyz_b[2 * HW + pN] : 0.f;

        const float ox = kx - sx_b[n0];
        const float oy = ky - sx_b[NPTS + n0];
        const float oz = kz - sx_b[2 * NPTS + n0];
        float h1[8];
#pragma unroll
        for (int r = 0; r < 8; r++) {
            float t = s_b1[r] + s_w1[3 * r] * ox + s_w1[3 * r + 1] * oy
                    + s_w1[3 * r + 2] * oz;
            h1[r] = fmaxf(t, 0.f);
        }
#pragma unroll
        for (int mm = 0; mm < 8; mm++) {
            const int m = m0 + mm;
            float t = s_b2[m];
#pragma unroll
            for (int r = 0; r < 8; r++) t += s_w2[m * 8 + r] * h1[r];
            s_h2[0][pp][j][m] = fmaxf(t, 0.f);
        }
        if (parity == 0 && sub == 0) {
            s_idx[0][pp][j] = p0;
            s_mf[0][pp][j]  = m0v ? 1.f : 0.f;
        }
    }
    asm volatile("bar.sync %0, %1;" :: "r"(1 + pp), "r"(64) : "memory");

    for (int pt = 0; pt < 8; pt++) {
        const int cur = pt & 1, nxt = cur ^ 1;

        // ---- fv gather for point pt (latency covered by phase1 below)
        float fv[16];
#pragma unroll
        for (int jj = 0; jj < 16; jj++) {
            const int p = s_idx[cur][pp][jj];
            fv[jj] = ftb[(size_t)p * 64 + c];
        }

        // ---- phase1(pt+1) into the other buffer
        if (pt < 7) {
            const int n1 = n0 + pt + 1;
            const float ox = xN - sx_b[n1];
            const float oy = yN - sx_b[NPTS + n1];
            const float oz = zN - sx_b[2 * NPTS + n1];
            const int pw = pN; const int mw_ = mN;
            float h1[8];
#pragma unroll
            for (int r = 0; r < 8; r++) {
                float t = s_b1[r] + s_w1[3 * r] * ox + s_w1[3 * r + 1] * oy
                        + s_w1[3 * r + 2] * oz;
                h1[r] = fmaxf(t, 0.f);
            }
#pragma unroll
            for (int mm = 0; mm < 8; mm++) {
                const int m = m0 + mm;
                float t = s_b2[m];
#pragma unroll
                for (int r = 0; r < 8; r++) t += s_w2[m * 8 + r] * h1[r];
                s_h2[nxt][pp][j][m] = fmaxf(t, 0.f);
            }
            if (parity == 0 && sub == 0) {
                s_idx[nxt][pp][j] = pw;
                s_mf[nxt][pp][j]  = mw_ ? 1.f : 0.f;
            }
            // prefetch point pt+2 (2-hop chain hidden behind phase2)
            if (pt < 6) {
                const long kb2 = kb0 + (long)(pt + 2) * KNN;
                pN = knn[kb2];
                mN = (mask[kb2] != 0);
                xN = mN ? xyz_b[pN] : 0.f;
                yN = mN ? xyz_b[HW + pN] : 0.f;
                zN = mN ? xyz_b[2 * HW + pN] : 0.f;
            }
        }

        // ---- mask-fold into fv
#pragma unroll
        for (int jj = 0; jj < 16; jj++) fv[jj] *= s_mf[cur][pp][jj];

        // ---- phase2(pt): w3 layer + max over k, 2 neighbors interleaved
        float acc = -3.4e38f;
#pragma unroll
        for (int jj = 0; jj < 16; jj += 2) {
            const ulonglong2* hA = reinterpret_cast<const ulonglong2*>(&s_h2[cur][pp][jj][0]);
            const ulonglong2* hB = reinterpret_cast<const ulonglong2*>(&s_h2[cur][pp][jj + 1][0]);
            ull a0 = 0ull, a1 = 0ull, bb0 = 0ull, bb1 = 0ull;
#pragma unroll
            for (int e = 0; e < 8; e++) {
                const ulonglong2 ha = hA[e];
                const ulonglong2 hb = hB[e];
                a0  = fma2(w3p[2 * e],     ha.x, a0);
                a1  = fma2(w3p[2 * e + 1], ha.y, a1);
                bb0 = fma2(w3p[2 * e],     hb.x, bb0);
                bb1 = fma2(w3p[2 * e + 1], hb.y, bb1);
            }
            const float2 ra0 = unpack2(a0),  ra1 = unpack2(a1);
            const float2 rb0 = unpack2(bb0), rb1 = unpack2(bb1);
            const float wgA = fmaxf(ra0.x + ra0.y + ra1.x + ra1.y + b3c, 0.f);
            const float wgB = fmaxf(rb0.x + rb0.y + rb1.x + rb1.y + b3c, 0.f);
            acc = fmaxf(acc, fv[jj] * wgA);
            acc = fmaxf(acc, fv[jj + 1] * wgB);
        }
        s_out[c][pp * 8 + pt] = acc;

        asm volatile("bar.sync %0, %1;" :: "r"(1 + pp), "r"(64) : "memory");
    }
    __syncthreads();

    float* outb = out + (size_t)b * 64 * NPTS;
    for (int i = tid; i < 2048; i += 256) {
        const int cc = i >> 5, s = i & 31;
        outb[(size_t)cc * NPTS + n_block + s] = s_out[cc][s];
    }
}

extern "C" void kernel_launch(void* const* d_in, const int* in_sizes, int n_in,
                              void* d_out, int out_size)
{
    const float* xyz  = (const float*)d_in[0];
    const float* feat = (const float*)d_in[1];
    const float* sx   = (const float*)d_in[2];
    const int*   knn  = (const int*)d_in[3];
    const int*   mask = (const int*)d_in[4];
    const float* mw = (const float*)d_in[5];
    const float* mb = (const float*)d_in[6];
    const float* w1 = (const float*)d_in[7];
    const float* b1 = (const float*)d_in[8];
    const float* w2 = (const float*)d_in[9];
    const float* b2 = (const float*)d_in[10];
    const float* w3 = (const float*)d_in[11];
    const float* b3 = (const float*)d_in[12];
    float* out = (float*)d_out;

    const int k1_smem = (64 * WS_PAD + 8 * FT_PAD + 256 * ST_PAD) * sizeof(float);
    cudaFuncSetAttribute(k_feat_mlp, cudaFuncAttributeMaxDynamicSharedMemorySize,
                         k1_smem);
    k_feat_mlp<<<375, 256, k1_smem>>>(feat, mw, mb);
    k_gather<<<750, 256>>>(xyz, sx, knn, mask, w1, b1, w2, b2, w3, b3, out);
}

// round 6
// speedup vs baseline: 1.2136x; 1.1262x over previous
#include <cuda_runtime.h>
#include <cstdint>

#define HW   48000
#define NPTS 12000
#define KNN  16

using ull = unsigned long long;

__device__ __forceinline__ ull pack2(float x, float y) {
    ull r; asm("mov.b64 %0, {%1, %2};" : "=l"(r) : "f"(x), "f"(y)); return r;
}
__device__ __forceinline__ float2 unpack2(ull v) {
    float2 r; asm("mov.b64 {%0, %1}, %2;" : "=f"(r.x), "=f"(r.y) : "l"(v)); return r;
}
__device__ __forceinline__ ull fma2(ull a, ull b, ull c) {
    ull d; asm("fma.rn.f32x2 %0, %1, %2, %3;" : "=l"(d) : "l"(a), "l"(b), "l"(c)); return d;
}
__device__ __forceinline__ void cp_async8(uint32_t dst_smem, const void* src) {
    asm volatile("cp.async.ca.shared.global [%0], [%1], 8;"
                 :: "r"(dst_smem), "l"(src) : "memory");
}
__device__ __forceinline__ void cp_commit() {
    asm volatile("cp.async.commit_group;" ::: "memory");
}
__device__ __forceinline__ void cp_wait0() {
    asm volatile("cp.async.wait_group 0;" ::: "memory");
}

// transposed feature map: [b*HW + p][64], contiguous 256B per pixel
__device__ __align__(16) float g_ft[2u * HW * 64u];

// ---------------------------------------------------------------------------
// Kernel 1: f = leaky_relu(mlp_w @ features + mlp_b), transposed to [pix][c]
// 375 blocks x 256 threads; thread: 4 px x 16 ch; direct stores (no stage).
// ---------------------------------------------------------------------------
#define WS_PAD 68
#define FT_PAD 264

__global__ void __launch_bounds__(256) k_feat_mlp(
    const float* __restrict__ feat,   // [B,64,HW]
    const float* __restrict__ mw,     // [64,64] [cout][cin]
    const float* __restrict__ mb)     // [64]
{
    extern __shared__ float sm[];
    float* ws    = sm;                       // [64][WS_PAD]
    float* ftile = ws + 64 * WS_PAD;         // [8][FT_PAD]
    __shared__ float bsh[64];

    const int tid = threadIdx.x;
    for (int i = tid; i < 4096; i += 256) {
        int c = i >> 6, ci = i & 63;
        ws[ci * WS_PAD + c] = mw[i];
    }
    if (tid < 64) bsh[tid] = mb[tid];

    const long gpix0 = (long)blockIdx.x * 256;
    const long lpix = gpix0 + tid;
    const int lb = (lpix >= HW) ? 1 : 0;
    const float* fbase = feat + (size_t)lb * 64 * HW + (lpix - (long)lb * HW);

    float pre[8];
#pragma unroll
    for (int t = 0; t < 8; t++) pre[t] = fbase[(size_t)t * HW];
    __syncthreads();

    const int cg  = tid & 3;
    const int pxq = tid >> 2;

    ull acc[4][8];
#pragma unroll
    for (int i = 0; i < 4; i++)
#pragma unroll
        for (int q = 0; q < 8; q++)
            acc[i][q] = pack2(bsh[16 * cg + 2 * q], bsh[16 * cg + 2 * q + 1]);

    for (int chunk = 0; chunk < 8; chunk++) {
#pragma unroll
        for (int t = 0; t < 8; t++) ftile[t * FT_PAD + tid] = pre[t];
        __syncthreads();

        if (chunk < 7) {
#pragma unroll
            for (int t = 0; t < 8; t++)
                pre[t] = fbase[(size_t)((chunk + 1) * 8 + t) * HW];
        }

#pragma unroll
        for (int cc = 0; cc < 8; cc++) {
            const float4 v = *reinterpret_cast<const float4*>(
                &ftile[cc * FT_PAD + 4 * pxq]);
            const ull* wrow = reinterpret_cast<const ull*>(
                &ws[(chunk * 8 + cc) * WS_PAD + 16 * cg]);
            ull wp[8];
#pragma unroll
            for (int q = 0; q < 8; q++) wp[q] = wrow[q];
            const ull vv0 = pack2(v.x, v.x), vv1 = pack2(v.y, v.y);
            const ull vv2 = pack2(v.z, v.z), vv3 = pack2(v.w, v.w);
#pragma unroll
            for (int q = 0; q < 8; q++) {
                acc[0][q] = fma2(wp[q], vv0, acc[0][q]);
                acc[1][q] = fma2(wp[q], vv1, acc[1][q]);
                acc[2][q] = fma2(wp[q], vv2, acc[2][q]);
                acc[3][q] = fma2(wp[q], vv3, acc[3][q]);
            }
        }
        __syncthreads();
    }

    // leaky relu + direct stores: 16 STG.128 per thread
    const size_t gbase = (size_t)gpix0 * 64;
#pragma unroll
    for (int i = 0; i < 4; i++) {
        const int px = 4 * pxq + i;
        float* dst = &g_ft[gbase + (size_t)px * 64 + 16 * cg];
#pragma unroll
        for (int qq = 0; qq < 4; qq++) {
            float2 t0 = unpack2(acc[i][2 * qq]);
            float2 t1 = unpack2(acc[i][2 * qq + 1]);
            t0.x = (t0.x >= 0.f) ? t0.x : 0.1f * t0.x;
            t0.y = (t0.y >= 0.f) ? t0.y : 0.1f * t0.y;
            t1.x = (t1.x >= 0.f) ? t1.x : 0.1f * t1.x;
            t1.y = (t1.y >= 0.f) ? t1.y : 0.1f * t1.y;
            float4 v4 = make_float4(t0.x, t0.y, t1.x, t1.y);
            *reinterpret_cast<float4*>(dst + 4 * qq) = v4;
        }
    }
}

// ---------------------------------------------------------------------------
// Kernel 2: gather + weight-net + f*wgt max over k.
// 750 blocks x 128 threads = 4 independent warps; warp = 8 points,
// 2 channels/lane, syncwarp-only pipeline, fv via cp.async into shared.
// ---------------------------------------------------------------------------
__global__ void __launch_bounds__(128, 4) k_gather(
    const float* __restrict__ xyz,    // [B,3,HW]
    const float* __restrict__ sxyz,   // [B,3,N]
    const int*   __restrict__ knn,    // [B,N,16]
    const int*   __restrict__ mask,   // [B,N,16] (bool widened to int32)
    const float* __restrict__ w1, const float* __restrict__ b1,
    const float* __restrict__ w2, const float* __restrict__ b2,
    const float* __restrict__ w3, const float* __restrict__ b3,
    float* __restrict__ out)          // [B,64,N]
{
    __shared__ float s_w1[24];
    __shared__ float s_b1[8];
    __shared__ float s_w2[256];
    __shared__ float s_b2[32];
    __shared__ __align__(16) float s_h2[4][2][16][36];
    __shared__ int    s_idx[4][2][16];
    __shared__ float  s_mf[4][2][16];
    __shared__ __align__(8) float2 s_fv[4][16][32];
    __shared__ float s_out[64][33];

    const int tid = threadIdx.x;
    const int w = tid >> 5, lane = tid & 31;

    if (tid < 24) s_w1[tid] = w1[tid];
    if (tid < 8)  s_b1[tid] = b1[tid];
    if (tid < 32) s_b2[tid] = b2[tid];
    s_w2[tid] = w2[tid];
    s_w2[tid + 128] = w2[tid + 128];

    // lane owns channels c0=2*lane, c1=c0+1; w3 rows packed over m-pairs
    const int c0 = 2 * lane;
    ull w3p0[16], w3p1[16];
    const ull* w3u = reinterpret_cast<const ull*>(w3);
#pragma unroll
    for (int e = 0; e < 16; e++) {
        w3p0[e] = w3u[c0 * 16 + e];
        w3p1[e] = w3u[(c0 + 1) * 16 + e];
    }
    const float b3c0 = b3[c0], b3c1 = b3[c0 + 1];
    __syncthreads();

    const int b = blockIdx.x / 375;
    const int n_block = (blockIdx.x % 375) * 32;

    const float* xyz_b = xyz + (size_t)b * 3 * HW;
    const float* sx_b  = sxyz + (size_t)b * 3 * NPTS;
    const float* ftb   = g_ft + (size_t)b * HW * 64;

    const int j = lane & 15, half = lane >> 4;
    const int m0 = half * 16;                 // this lane: h2[j][m0..m0+15]
    const int n0 = n_block + w * 8;
    const long kb0 = ((long)b * NPTS + n0) * KNN + j;

    const uint32_t fv_base = (uint32_t)__cvta_generic_to_shared(&s_fv[w][0][lane]);

    // pipeline registers (point pt+1)
    int pN, mN; float xN, yN, zN;

    // --- prologue: phase1(point 0) into buf0; prefetch point 1
    {
        const int p0 = knn[kb0];
        const int mv = (mask[kb0] != 0);
        const float kx = mv ? xyz_b[p0] : 0.f;
        const float ky = mv ? xyz_b[HW + p0] : 0.f;
        const float kz = mv ? xyz_b[2 * HW + p0] : 0.f;

        pN = knn[kb0 + KNN];
        mN = (mask[kb0 + KNN] != 0);
        xN = mN ? xyz_b[pN] : 0.f;
        yN = mN ? xyz_b[HW + pN] : 0.f;
        zN = mN ? xyz_b[2 * HW + pN] : 0.f;

        const float ox = kx - sx_b[n0];
        const float oy = ky - sx_b[NPTS + n0];
        const float oz = kz - sx_b[2 * NPTS + n0];
        float h1[8];
#pragma unroll
        for (int r = 0; r < 8; r++) {
            float t = s_b1[r] + s_w1[3 * r] * ox + s_w1[3 * r + 1] * oy
                    + s_w1[3 * r + 2] * oz;
            h1[r] = fmaxf(t, 0.f);
        }
#pragma unroll
        for (int mm = 0; mm < 16; mm++) {
            const int m = m0 + mm;
            float t = s_b2[m];
#pragma unroll
            for (int r = 0; r < 8; r++) t += s_w2[m * 8 + r] * h1[r];
            s_h2[w][0][j][m] = fmaxf(t, 0.f);
        }
        if (half == 0) {
            s_idx[w][0][j] = p0;
            s_mf[w][0][j]  = mv ? 1.f : 0.f;
        }
    }
    __syncwarp();

    for (int pt = 0; pt < 8; pt++) {
        const int cur = pt & 1, nxt = cur ^ 1;

        // ---- A: issue fv gathers for point pt via cp.async (no regs)
#pragma unroll
        for (int jj = 0; jj < 16; jj++) {
            const int p = s_idx[w][cur][jj];
            cp_async8(fv_base + (uint32_t)jj * sizeof(float2) * 32,
                      ftb + (size_t)p * 64 + c0);
        }
        cp_commit();

        // ---- B: phase1(pt+1) into other buffer; prefetch pt+2
        if (pt < 7) {
            const int n1 = n0 + pt + 1;
            const int pc = pN; const int mc = mN;
            const float xc = xN, yc = yN, zc = zN;
            if (pt < 6) {
                const long kb2 = kb0 + (long)(pt + 2) * KNN;
                pN = knn[kb2];
                mN = (mask[kb2] != 0);
                xN = mN ? xyz_b[pN] : 0.f;
                yN = mN ? xyz_b[HW + pN] : 0.f;
                zN = mN ? xyz_b[2 * HW + pN] : 0.f;
            }
            const float ox = xc - sx_b[n1];
            const float oy = yc - sx_b[NPTS + n1];
            const float oz = zc - sx_b[2 * NPTS + n1];
            float h1[8];
#pragma unroll
            for (int r = 0; r < 8; r++) {
                float t = s_b1[r] + s_w1[3 * r] * ox + s_w1[3 * r + 1] * oy
                        + s_w1[3 * r + 2] * oz;
                h1[r] = fmaxf(t, 0.f);
            }
#pragma unroll
            for (int mm = 0; mm < 16; mm++) {
                const int m = m0 + mm;
                float t = s_b2[m];
#pragma unroll
                for (int r = 0; r < 8; r++) t += s_w2[m * 8 + r] * h1[r];
                s_h2[w][nxt][j][m] = fmaxf(t, 0.f);
            }
            if (half == 0) {
                s_idx[w][nxt][j] = pc;
                s_mf[w][nxt][j]  = mc ? 1.f : 0.f;
            }
        }

        cp_wait0();

        // ---- D: phase2(pt): w3 layer + f*wgt, max over k
        float accx = -3.4e38f, accy = -3.4e38f;
#pragma unroll 2
        for (int jj = 0; jj < 16; jj += 2) {
            const float mfA = s_mf[w][cur][jj];
            const float mfB = s_mf[w][cur][jj + 1];
            float2 fA = s_fv[w][jj][lane];
            float2 fB = s_fv[w][jj + 1][lane];
            fA.x *= mfA; fA.y *= mfA;
            fB.x *= mfB; fB.y *= mfB;
            const ulonglong2* hA =
                reinterpret_cast<const ulonglong2*>(&s_h2[w][cur][jj][0]);
            const ulonglong2* hB =
                reinterpret_cast<const ulonglong2*>(&s_h2[w][cur][jj + 1][0]);
            ull ax0 = 0ull, ax1 = 0ull, ay0 = 0ull, ay1 = 0ull;
            ull bx0 = 0ull, bx1 = 0ull, by0 = 0ull, by1 = 0ull;
#pragma unroll
            for (int e = 0; e < 8; e++) {
                const ulonglong2 ha = hA[e];
                const ulonglong2 hb = hB[e];
                ax0 = fma2(w3p0[2 * e],     ha.x, ax0);
                ax1 = fma2(w3p0[2 * e + 1], ha.y, ax1);
                ay0 = fma2(w3p1[2 * e],     ha.x, ay0);
                ay1 = fma2(w3p1[2 * e + 1], ha.y, ay1);
                bx0 = fma2(w3p0[2 * e],     hb.x, bx0);
                bx1 = fma2(w3p0[2 * e + 1], hb.y, bx1);
                by0 = fma2(w3p1[2 * e],     hb.x, by0);
                by1 = fma2(w3p1[2 * e + 1], hb.y, by1);
            }
            const float2 rax0 = unpack2(ax0), rax1 = unpack2(ax1);
            const float2 ray0 = unpack2(ay0), ray1 = unpack2(ay1);
            const float2 rbx0 = unpack2(bx0), rbx1 = unpack2(bx1);
            const float2 rby0 = unpack2(by0), rby1 = unpack2(by1);
            const float wgA0 = fmaxf(rax0.x + rax0.y + rax1.x + rax1.y + b3c0, 0.f);
            const float wgA1 = fmaxf(ray0.x + ray0.y + ray1.x + ray1.y + b3c1, 0.f);
            const float wgB0 = fmaxf(rbx0.x + rbx0.y + rbx1.x + rbx1.y + b3c0, 0.f);
            const float wgB1 = fmaxf(rby0.x + rby0.y + rby1.x + rby1.y + b3c1, 0.f);
            accx = fmaxf(accx, fA.x * wgA0);
            accy = fmaxf(accy, fA.y * wgA1);
            accx = fmaxf(accx, fB.x * wgB0);
            accy = fmaxf(accy, fB.y * wgB1);
        }
        s_out[c0][w * 8 + pt]     = accx;
        s_out[c0 + 1][w * 8 + pt] = accy;

        __syncwarp();
    }
    __syncthreads();

    // coalesced output: [B,64,N]
    float* outb = out + (size_t)b * 64 * NPTS;
    for (int i = tid; i < 2048; i += 128) {
        const int cc = i >> 5, s = i & 31;
        outb[(size_t)cc * NPTS + n_block + s] = s_out[cc][s];
    }
}

extern "C" void kernel_launch(void* const* d_in, const int* in_sizes, int n_in,
                              void* d_out, int out_size)
{
    const float* xyz  = (const float*)d_in[0];
    const float* feat = (const float*)d_in[1];
    const float* sx   = (const float*)d_in[2];
    const int*   knn  = (const int*)d_in[3];
    const int*   mask = (const int*)d_in[4];
    const float* mw = (const float*)d_in[5];
    const float* mb = (const float*)d_in[6];
    const float* w1 = (const float*)d_in[7];
    const float* b1 = (const float*)d_in[8];
    const float* w2 = (const float*)d_in[9];
    const float* b2 = (const float*)d_in[10];
    const float* w3 = (const float*)d_in[11];
    const float* b3 = (const float*)d_in[12];
    float* out = (float*)d_out;

    const int k1_smem = (64 * WS_PAD + 8 * FT_PAD) * sizeof(float);
    k_feat_mlp<<<375, 256, k1_smem>>>(feat, mw, mb);
    k_gather<<<750, 128>>>(xyz, sx, knn, mask, w1, b1, w2, b2, w3, b3, out);
}

// round 8
// speedup vs baseline: 1.4038x; 1.1567x over previous
#include <cuda_runtime.h>
#include <cstdint>

#define HW   48000
#define NPTS 12000
#define KNN  16

using ull = unsigned long long;

__device__ __forceinline__ ull pack2(float x, float y) {
    ull r; asm("mov.b64 %0, {%1, %2};" : "=l"(r) : "f"(x), "f"(y)); return r;
}
__device__ __forceinline__ float2 unpack2(ull v) {
    float2 r; asm("mov.b64 {%0, %1}, %2;" : "=f"(r.x), "=f"(r.y) : "l"(v)); return r;
}
__device__ __forceinline__ ull fma2(ull a, ull b, ull c) {
    ull d; asm("fma.rn.f32x2 %0, %1, %2, %3;" : "=l"(d) : "l"(a), "l"(b), "l"(c)); return d;
}
__device__ __forceinline__ ull add2(ull a, ull b) {
    ull d; asm("add.rn.f32x2 %0, %1, %2;" : "=l"(d) : "l"(a), "l"(b)); return d;
}
__device__ __forceinline__ void cp_async8(uint32_t dst_smem, const void* src) {
    asm volatile("cp.async.ca.shared.global [%0], [%1], 8;"
                 :: "r"(dst_smem), "l"(src) : "memory");
}
__device__ __forceinline__ void cp_commit() {
    asm volatile("cp.async.commit_group;" ::: "memory");
}
__device__ __forceinline__ void cp_wait0() {
    asm volatile("cp.async.wait_group 0;" ::: "memory");
}

// transposed feature map: [b*HW + p][64], contiguous 256B per pixel
__device__ __align__(16) float g_ft[2u * HW * 64u];

// ---------------------------------------------------------------------------
// Kernel 1: f = leaky_relu(mlp_w @ features + mlp_b), transposed to [pix][c]
// 375 blocks x 256 threads; thread: 8 px x 8 ch.
// ws groups at 10-float stride -> conflict-free LDS.64 across the 8 ch-groups.
// ---------------------------------------------------------------------------
#define WS_PITCH 80
#define FT_PAD 264

__global__ void __launch_bounds__(256, 2) k_feat_mlp(
    const float* __restrict__ feat,   // [B,64,HW]
    const float* __restrict__ mw,     // [64,64] [cout][cin]
    const float* __restrict__ mb)     // [64]
{
    extern __shared__ float sm[];
    float* ws    = sm;                       // [64][WS_PITCH]
    float* ftile = ws + 64 * WS_PITCH;       // [8][FT_PAD]
    __shared__ float bsh[64];

    const int tid = threadIdx.x;
    for (int i = tid; i < 4096; i += 256) {
        int c = i >> 6, ci = i & 63;
        ws[ci * WS_PITCH + 10 * (c >> 3) + (c & 7)] = mw[i];
    }
    if (tid < 64) bsh[tid] = mb[tid];

    const long gpix0 = (long)blockIdx.x * 256;
    const long lpix = gpix0 + tid;
    const int lb = (lpix >= HW) ? 1 : 0;
    const float* fbase = feat + (size_t)lb * 64 * HW + (lpix - (long)lb * HW);

    float pre[8];
#pragma unroll
    for (int t = 0; t < 8; t++) pre[t] = fbase[(size_t)t * HW];
    __syncthreads();

    const int cg  = tid & 7;          // channel group (8 ch)
    const int pxg = tid >> 3;         // pixel group (8 px)

    ull acc[8][4];
#pragma unroll
    for (int p = 0; p < 8; p++)
#pragma unroll
        for (int q = 0; q < 4; q++)
            acc[p][q] = pack2(bsh[8 * cg + 2 * q], bsh[8 * cg + 2 * q + 1]);

    for (int chunk = 0; chunk < 8; chunk++) {
#pragma unroll
        for (int t = 0; t < 8; t++) ftile[t * FT_PAD + tid] = pre[t];
        __syncthreads();

        if (chunk < 7) {
#pragma unroll
            for (int t = 0; t < 8; t++)
                pre[t] = fbase[(size_t)((chunk + 1) * 8 + t) * HW];
        }

#pragma unroll
        for (int cc = 0; cc < 8; cc++) {
            const ull* wrow = reinterpret_cast<const ull*>(
                &ws[(chunk * 8 + cc) * WS_PITCH + 10 * cg]);
            ull wp[4];
#pragma unroll
            for (int q = 0; q < 4; q++) wp[q] = wrow[q];
            const float4 v0 = *reinterpret_cast<const float4*>(
                &ftile[cc * FT_PAD + 8 * pxg]);
            const float4 v1 = *reinterpret_cast<const float4*>(
                &ftile[cc * FT_PAD + 8 * pxg + 4]);
            const float vv[8] = {v0.x, v0.y, v0.z, v0.w, v1.x, v1.y, v1.z, v1.w};
#pragma unroll
            for (int p = 0; p < 8; p++) {
                const ull vp = pack2(vv[p], vv[p]);
#pragma unroll
                for (int q = 0; q < 4; q++)
                    acc[p][q] = fma2(wp[q], vp, acc[p][q]);
            }
        }
        __syncthreads();
    }

    // leaky relu + coalesced stores: per px, 2 STG.128 (8 ch)
    const size_t gbase = (size_t)gpix0 * 64;
#pragma unroll
    for (int p = 0; p < 8; p++) {
        const int px = 8 * pxg + p;
        float* dst = &g_ft[gbase + (size_t)px * 64 + 8 * cg];
        float2 t0 = unpack2(acc[p][0]);
        float2 t1 = unpack2(acc[p][1]);
        float2 t2 = unpack2(acc[p][2]);
        float2 t3 = unpack2(acc[p][3]);
        t0.x = (t0.x >= 0.f) ? t0.x : 0.1f * t0.x;
        t0.y = (t0.y >= 0.f) ? t0.y : 0.1f * t0.y;
        t1.x = (t1.x >= 0.f) ? t1.x : 0.1f * t1.x;
        t1.y = (t1.y >= 0.f) ? t1.y : 0.1f * t1.y;
        t2.x = (t2.x >= 0.f) ? t2.x : 0.1f * t2.x;
        t2.y = (t2.y >= 0.f) ? t2.y : 0.1f * t2.y;
        t3.x = (t3.x >= 0.f) ? t3.x : 0.1f * t3.x;
        t3.y = (t3.y >= 0.f) ? t3.y : 0.1f * t3.y;
        *reinterpret_cast<float4*>(dst)     = make_float4(t0.x, t0.y, t1.x, t1.y);
        *reinterpret_cast<float4*>(dst + 4) = make_float4(t2.x, t2.y, t3.x, t3.y);
    }
}

// ---------------------------------------------------------------------------
// Kernel 2: gather + weight-net + f*wgt max over k.
// 750 blocks x 128 threads = 4 independent warps; warp = 8 points,
// 2 channels/lane, syncwarp-only pipeline, fv via cp.async into shared.
// w2 kept twice in smem (second copy at +260 floats) -> conflict-free halves.
// ---------------------------------------------------------------------------
__global__ void __launch_bounds__(128, 5) k_gather(
    const float* __restrict__ xyz,    // [B,3,HW]
    const float* __restrict__ sxyz,   // [B,3,N]
    const int*   __restrict__ knn,    // [B,N,16]
    const int*   __restrict__ mask,   // [B,N,16] (bool widened to int32)
    const float* __restrict__ w1, const float* __restrict__ b1,
    const float* __restrict__ w2, const float* __restrict__ b2,
    const float* __restrict__ w3, const float* __restrict__ b3,
    float* __restrict__ out)          // [B,64,N]
{
    __shared__ float s_w1[24];
    __shared__ float s_b1[8];
    __shared__ __align__(8) float s_w2[520];   // copy0 @0, copy1 @260
    __shared__ float s_b2[32];
    __shared__ __align__(16) float s_h2[4][2][16][36];
    __shared__ int    s_idx[4][2][16];
    __shared__ float  s_mf[4][2][16];
    __shared__ __align__(8) float2 s_fv[4][16][32];

    const int tid = threadIdx.x;
    const int w = tid >> 5, lane = tid & 31;

    if (tid < 24) s_w1[tid] = w1[tid];
    if (tid < 8)  s_b1[tid] = b1[tid];
    if (tid < 32) s_b2[tid] = b2[tid];
    { const int i = tid, i2 = tid + 128;
      s_w2[i] = w2[i];       s_w2[260 + i] = w2[i];
      s_w2[i2] = w2[i2];     s_w2[260 + i2] = w2[i2]; }

    // lane owns channels c0=2*lane, c1=c0+1; w3 rows packed over m-pairs
    const int c0 = 2 * lane;
    ull w3p0[16], w3p1[16];
    const ull* w3u = reinterpret_cast<const ull*>(w3);
#pragma unroll
    for (int e = 0; e < 16; e++) {
        w3p0[e] = w3u[c0 * 16 + e];
        w3p1[e] = w3u[(c0 + 1) * 16 + e];
    }
    const float b3c0 = b3[c0], b3c1 = b3[c0 + 1];
    __syncthreads();

    const int b = blockIdx.x / 375;
    const int n_block = (blockIdx.x % 375) * 32;

    const float* xyz_b = xyz + (size_t)b * 3 * HW;
    const float* sx_b  = sxyz + (size_t)b * 3 * NPTS;
    const float* ftb   = g_ft + (size_t)b * HW * 64;

    const int j = lane & 15, half = lane >> 4;
    const int m0 = half * 16;
    // conflict-free w2 base: half0 reads copy0 (m*8 in [0,128)),
    // half1 reads copy1 at +260 (m*8 in [128,256) -> floats 388..515).
    const float* w2base = s_w2 + (half ? 260 : 0);
    const int n0 = n_block + w * 8;
    const long kb0 = ((long)b * NPTS + n0) * KNN + j;

    const uint32_t fv_base = (uint32_t)__cvta_generic_to_shared(&s_fv[w][0][lane]);

    // pipeline registers (point pt+1)
    int pN, mN; float xN, yN, zN;

    // --- prologue: phase1(point 0) into buf0; prefetch point 1
    {
        const int p0 = knn[kb0];
        const int mv = (mask[kb0] != 0);
        const float kx = mv ? xyz_b[p0] : 0.f;
        const float ky = mv ? xyz_b[HW + p0] : 0.f;
        const float kz = mv ? xyz_b[2 * HW + p0] : 0.f;

        pN = knn[kb0 + KNN];
        mN = (mask[kb0 + KNN] != 0);
        xN = mN ? xyz_b[pN] : 0.f;
        yN = mN ? xyz_b[HW + pN] : 0.f;
        zN = mN ? xyz_b[2 * HW + pN] : 0.f;

        const float ox = kx - sx_b[n0];
        const float oy = ky - sx_b[NPTS + n0];
        const float oz = kz - sx_b[2 * NPTS + n0];
        ull h1p[4];
#pragma unroll
        for (int rr = 0; rr < 4; rr++) {
            float t0 = s_b1[2 * rr] + s_w1[6 * rr] * ox
                     + s_w1[6 * rr + 1] * oy + s_w1[6 * rr + 2] * oz;
            float t1 = s_b1[2 * rr + 1] + s_w1[6 * rr + 3] * ox
                     + s_w1[6 * rr + 4] * oy + s_w1[6 * rr + 5] * oz;
            h1p[rr] = pack2(fmaxf(t0, 0.f), fmaxf(t1, 0.f));
        }
#pragma unroll
        for (int mm = 0; mm < 16; mm++) {
            const int m = m0 + mm;
            const ull* wrow = reinterpret_cast<const ull*>(w2base + m * 8);
            ull a = 0ull;
#pragma unroll
            for (int rr = 0; rr < 4; rr++) a = fma2(wrow[rr], h1p[rr], a);
            const float2 ra = unpack2(a);
            s_h2[w][0][j][m] = fmaxf(ra.x + ra.y + s_b2[m], 0.f);
        }
        if (half == 0) {
            s_idx[w][0][j] = p0;
            s_mf[w][0][j]  = mv ? 1.f : 0.f;
        }
    }
    __syncwarp();

    float* outb = out + (size_t)b * 64 * NPTS + n0;

    for (int pt = 0; pt < 8; pt++) {
        const int cur = pt & 1, nxt = cur ^ 1;

        // ---- A: issue fv gathers for point pt via cp.async (no regs)
#pragma unroll
        for (int jj = 0; jj < 16; jj++) {
            const int p = s_idx[w][cur][jj];
            cp_async8(fv_base + (uint32_t)jj * sizeof(float2) * 32,
                      ftb + (size_t)p * 64 + c0);
        }
        cp_commit();

        // ---- B: phase1(pt+1) into other buffer; prefetch pt+2
        if (pt < 7) {
            const int n1 = n0 + pt + 1;
            const int pc = pN; const int mc = mN;
            const float xc = xN, yc = yN, zc = zN;
            if (pt < 6) {
                const long kb2 = kb0 + (long)(pt + 2) * KNN;
                pN = knn[kb2];
                mN = (mask[kb2] != 0);
                xN = mN ? xyz_b[pN] : 0.f;
                yN = mN ? xyz_b[HW + pN] : 0.f;
                zN = mN ? xyz_b[2 * HW + pN] : 0.f;
            }
            const float ox = xc - sx_b[n1];
            const float oy = yc - sx_b[NPTS + n1];
            const float oz = zc - sx_b[2 * NPTS + n1];
            ull h1p[4];
#pragma unroll
            for (int rr = 0; rr < 4; rr++) {
                float t0 = s_b1[2 * rr] + s_w1[6 * rr] * ox
                         + s_w1[6 * rr + 1] * oy + s_w1[6 * rr + 2] * oz;
                float t1 = s_b1[2 * rr + 1] + s_w1[6 * rr + 3] * ox
                         + s_w1[6 * rr + 4] * oy + s_w1[6 * rr + 5] * oz;
                h1p[rr] = pack2(fmaxf(t0, 0.f), fmaxf(t1, 0.f));
            }
#pragma unroll
            for (int mm = 0; mm < 16; mm++) {
                const int m = m0 + mm;
                const ull* wrow = reinterpret_cast<const ull*>(w2base + m * 8);
                ull a = 0ull;
#pragma unroll
                for (int rr = 0; rr < 4; rr++) a = fma2(wrow[rr], h1p[rr], a);
                const float2 ra = unpack2(a);
                s_h2[w][nxt][j][m] = fmaxf(ra.x + ra.y + s_b2[m], 0.f);
            }
            if (half == 0) {
                s_idx[w][nxt][j] = pc;
                s_mf[w][nxt][j]  = mc ? 1.f : 0.f;
            }
        }

        cp_wait0();

        // ---- D: phase2(pt): w3 layer + f*wgt, max over k
        float accx = -3.4e38f, accy = -3.4e38f;
#pragma unroll 2
        for (int jj = 0; jj < 16; jj += 2) {
            const float mfA = s_mf[w][cur][jj];
            const float mfB = s_mf[w][cur][jj + 1];
            float2 fA = s_fv[w][jj][lane];
            float2 fB = s_fv[w][jj + 1][lane];
            fA.x *= mfA; fA.y *= mfA;
            fB.x *= mfB; fB.y *= mfB;
            const ulonglong2* hA =
                reinterpret_cast<const ulonglong2*>(&s_h2[w][cur][jj][0]);
            const ulonglong2* hB =
                reinterpret_cast<const ulonglong2*>(&s_h2[w][cur][jj + 1][0]);
            ull ax0 = pack2(b3c0, 0.f), ax1 = 0ull;
            ull ay0 = pack2(b3c1, 0.f), ay1 = 0ull;
            ull bx0 = pack2(b3c0, 0.f), bx1 = 0ull;
            ull by0 = pack2(b3c1, 0.f), by1 = 0ull;
#pragma unroll
            for (int e = 0; e < 8; e++) {
                const ulonglong2 ha = hA[e];
                const ulonglong2 hb = hB[e];
                ax0 = fma2(w3p0[2 * e],     ha.x, ax0);
                ax1 = fma2(w3p0[2 * e + 1], ha.y, ax1);
                ay0 = fma2(w3p1[2 * e],     ha.x, ay0);
                ay1 = fma2(w3p1[2 * e + 1], ha.y, ay1);
                bx0 = fma2(w3p0[2 * e],     hb.x, bx0);
                bx1 = fma2(w3p0[2 * e + 1], hb.y, bx1);
                by0 = fma2(w3p1[2 * e],     hb.x, by0);
                by1 = fma2(w3p1[2 * e + 1], hb.y, by1);
            }
            const float2 sax = unpack2(add2(ax0, ax1));
            const float2 say = unpack2(add2(ay0, ay1));
            const float2 sbx = unpack2(add2(bx0, bx1));
            const float2 sby = unpack2(add2(by0, by1));
            const float wgA0 = fmaxf(sax.x + sax.y, 0.f);
            const float wgA1 = fmaxf(say.x + say.y, 0.f);
            const float wgB0 = fmaxf(sbx.x + sbx.y, 0.f);
            const float wgB1 = fmaxf(sby.x + sby.y, 0.f);
            accx = fmaxf(accx, fA.x * wgA0);
            accy = fmaxf(accy, fA.y * wgA1);
            accx = fmaxf(accx, fB.x * wgB0);
            accy = fmaxf(accy, fB.y * wgB1);
        }
        outb[(size_t)c0 * NPTS + pt]       = accx;
        outb[(size_t)(c0 + 1) * NPTS + pt] = accy;

        __syncwarp();
    }
}

extern "C" void kernel_launch(void* const* d_in, const int* in_sizes, int n_in,
                              void* d_out, int out_size)
{
    const float* xyz  = (const float*)d_in[0];
    const float* feat = (const float*)d_in[1];
    const float* sx   = (const float*)d_in[2];
    const int*   knn  = (const int*)d_in[3];
    const int*   mask = (const int*)d_in[4];
    const float* mw = (const float*)d_in[5];
    const float* mb = (const float*)d_in[6];
    const float* w1 = (const float*)d_in[7];
    const float* b1 = (const float*)d_in[8];
    const float* w2 = (const float*)d_in[9];
    const float* b2 = (const float*)d_in[10];
    const float* w3 = (const float*)d_in[11];
    const float* b3 = (const float*)d_in[12];
    float* out = (float*)d_out;

    const int k1_smem = (64 * WS_PITCH + 8 * FT_PAD) * sizeof(float);
    k_feat_mlp<<<375, 256, k1_smem>>>(feat, mw, mb);
    k_gather<<<750, 128>>>(xyz, sx, knn, mask, w1, b1, w2, b2, w3, b3, out);
}